// round 13
// baseline (speedup 1.0000x reference)
#include <cuda_runtime.h>
#include <cstdint>

// ---------------------------------------------------------------------------
// Problem constants: B=4, E=400000, N_NODES=50000, N_REL=500, D=64, D_LG=256,
// K_PER_VI=20, N_MEM=131072. Scratch via device globals (no allocation).
// ---------------------------------------------------------------------------
__device__ float g_hc[131072 * 64];   // tanh(hidden_con @ Wc + bc)
__device__ float g_hu[50000 * 64];    // tanh(hidden_uncon @ Wu + bu)

// ---------------- packed f32x2 helpers (sm_103a) ----------------
__device__ __forceinline__ void unpack2(unsigned long long u, float& x, float& y) {
    asm("mov.b64 {%0,%1}, %2;" : "=f"(x), "=f"(y) : "l"(u));
}
__device__ __forceinline__ unsigned long long dup2(float x) {
    unsigned long long u;
    asm("mov.b64 %0, {%1,%1};" : "=l"(u) : "f"(x));
    return u;
}
__device__ __forceinline__ void fma2(unsigned long long& d,
                                     unsigned long long a, unsigned long long b) {
    asm("fma.rn.f32x2 %0, %1, %2, %0;" : "+l"(d) : "l"(a), "l"(b));
}

__device__ __forceinline__ float tanh_fast(float x) {
    float e = __expf(-2.0f * fabsf(x));
    float t = (1.0f - e) / (1.0f + e);
    return copysignf(t, x);
}

// ---------------------------------------------------------------------------
// Projection v9: cp.async double-buffered pipeline; thread tile RESHAPED to
// 4 rows x 8 cols (was 2x16) to halve W LDS traffic (L1tex was 71% = binder).
// Per kk per warp: 2 W-LDS.128 + 1 x-LDS.128 + 4 dup movs + 16 FFMA2.
// Lane map: cg = lane&7 (8-col group), rg = lane>>3 (4 consecutive rows);
// warp covers rows [warp*16, warp*16+16), block = 128 rows x 64 cols.
// Smem unchanged: Xbuf row-major [128][36] x2, Wbuf [32][64] x2 = 53,248 B.
// ---------------------------------------------------------------------------
template <int K>
__device__ __forceinline__ void proj_tile_async(
    const float* __restrict__ X, const float* __restrict__ W,
    const float* __restrict__ bias, float* __restrict__ out,
    int rows, int bid, float* sm)
{
    constexpr int NC = K / 32;
    float* xbuf[2] = {sm, sm + 4608};
    float* wbuf[2] = {sm + 9216, sm + 11264};

    const int tid  = threadIdx.x;
    const int lane = tid & 31;
    const int warp = tid >> 5;
    const int cg   = lane & 7;            // 0..7: 8-col group
    const int rg   = lane >> 3;           // 0..3: 4-row group
    const int r0   = bid * 128;
    const int row0 = warp * 16 + rg * 4;  // rows row0..row0+3

    unsigned int xs[2], wsm[2];
    xs[0]  = (unsigned int)__cvta_generic_to_shared(xbuf[0]);
    xs[1]  = (unsigned int)__cvta_generic_to_shared(xbuf[1]);
    wsm[0] = (unsigned int)__cvta_generic_to_shared(wbuf[0]);
    wsm[1] = (unsigned int)__cvta_generic_to_shared(wbuf[1]);

    auto issue_chunk = [&](int c) {
        const int k0 = c * 32;
        const unsigned int xdst = xs[c & 1];
        const unsigned int wdst = wsm[c & 1];
#pragma unroll
        for (int p = 0; p < 4; p++) {
            int idx = tid + p * 256;
            int row = idx >> 3, c16 = idx & 7;
            int grow = r0 + row;
            int sz = (grow < rows) ? 16 : 0;
            if (grow >= rows) grow = rows - 1;
            const float* src = X + (size_t)grow * K + k0 + 4 * c16;
            unsigned int dst = xdst + (unsigned int)(row * 36 + 4 * c16) * 4u;
            asm volatile("cp.async.ca.shared.global [%0], [%1], 16, %2;"
                         :: "r"(dst), "l"(src), "r"(sz) : "memory");
        }
#pragma unroll
        for (int p = 0; p < 2; p++) {
            int idx = tid + p * 256;
            const float* src = W + (size_t)k0 * 64 + 4 * idx;
            unsigned int dst = wdst + (unsigned int)(4 * idx) * 4u;
            asm volatile("cp.async.ca.shared.global [%0], [%1], 16;"
                         :: "r"(dst), "l"(src) : "memory");
        }
        asm volatile("cp.async.commit_group;" ::: "memory");
    };

    unsigned long long acc[4][4];   // 4 rows x 8 cols (4 f32x2 pairs/row)
#pragma unroll
    for (int r = 0; r < 4; r++)
#pragma unroll
        for (int j = 0; j < 4; j++) acc[r][j] = 0ull;

    issue_chunk(0);

#pragma unroll
    for (int c = 0; c < NC; c++) {
        if (c + 1 < NC) {
            issue_chunk(c + 1);
            asm volatile("cp.async.wait_group 1;" ::: "memory");
        } else {
            asm volatile("cp.async.wait_group 0;" ::: "memory");
        }
        __syncthreads();

        const float* xrow = xbuf[c & 1] + (size_t)row0 * 36;
        const float* wb   = wbuf[c & 1] + cg * 8;
#pragma unroll
        for (int k4 = 0; k4 < 8; k4++) {
            float4 xq[4];
#pragma unroll
            for (int r = 0; r < 4; r++)
                xq[r] = *reinterpret_cast<const float4*>(xrow + (size_t)r * 36 + 4 * k4);
            const float x0[4] = {xq[0].x, xq[0].y, xq[0].z, xq[0].w};
            const float x1[4] = {xq[1].x, xq[1].y, xq[1].z, xq[1].w};
            const float x2[4] = {xq[2].x, xq[2].y, xq[2].z, xq[2].w};
            const float x3[4] = {xq[3].x, xq[3].y, xq[3].z, xq[3].w};
#pragma unroll
            for (int t = 0; t < 4; t++) {
                const ulonglong2* wp = reinterpret_cast<const ulonglong2*>(
                    wb + (size_t)(4 * k4 + t) * 64);
                ulonglong2 wA = wp[0], wB = wp[1];
                unsigned long long wv[4] = {wA.x, wA.y, wB.x, wB.y};
                unsigned long long d0 = dup2(x0[t]);
                unsigned long long d1 = dup2(x1[t]);
                unsigned long long d2 = dup2(x2[t]);
                unsigned long long d3 = dup2(x3[t]);
#pragma unroll
                for (int j = 0; j < 4; j++) fma2(acc[0][j], d0, wv[j]);
#pragma unroll
                for (int j = 0; j < 4; j++) fma2(acc[1][j], d1, wv[j]);
#pragma unroll
                for (int j = 0; j < 4; j++) fma2(acc[2][j], d2, wv[j]);
#pragma unroll
                for (int j = 0; j < 4; j++) fma2(acc[3][j], d3, wv[j]);
            }
        }
        __syncthreads();
    }

    // ---- epilogue: bias + tanh, stage to smem [128][68], coalesced stores --
    float bv[8];
#pragma unroll
    for (int j = 0; j < 8; j++) bv[j] = __ldg(&bias[cg * 8 + j]);
#pragma unroll
    for (int r = 0; r < 4; r++) {
        int row = row0 + r;
        float* dst = &sm[(size_t)row * 68 + cg * 8];
#pragma unroll
        for (int j = 0; j < 4; j++) {
            float a, b;
            unpack2(acc[r][j], a, b);
            *reinterpret_cast<float2*>(dst + 2 * j) =
                make_float2(tanh_fast(a + bv[2 * j]), tanh_fast(b + bv[2 * j + 1]));
        }
    }
    __syncthreads();
#pragma unroll
    for (int i = 0; i < 8; i++) {
        int idx = tid + i * 256;
        int row = idx >> 4, c4 = idx & 15;
        if (r0 + row < rows)
            *reinterpret_cast<float4*>(&out[(size_t)(r0 + row) * 64 + 4 * c4]) =
                *reinterpret_cast<const float4*>(&sm[(size_t)row * 68 + 4 * c4]);
    }
}

__global__ void __launch_bounds__(256, 3) proj_both_kernel(
    const float* __restrict__ Xc, const float* __restrict__ Wc,
    const float* __restrict__ bc, int rows_c,
    const float* __restrict__ Xu, const float* __restrict__ Wu,
    const float* __restrict__ bu, int rows_u, int nb_u)
{
    extern __shared__ float sm[];
    if ((int)blockIdx.x < nb_u) {
        proj_tile_async<256>(Xu, Wu, bu, g_hu, rows_u, blockIdx.x, sm);
    } else {
        proj_tile_async<64>(Xc, Wc, bc, g_hc, rows_c, blockIdx.x - nb_u, sm);
    }
}

// Tiny no-op kernel: keeps ncu's "-s 5 -c 1" capture landing on proj.
__global__ void capture_align_kernel() {}

// ---------------------------------------------------------------------------
// Edge kernel v4 (known 64us): 2 segments per 320-thread block, 5 warps/
// segment, 4 edges/warp. Weights staged in smem once per block; gathers
// front-batched; out_b dropped (softmax-invariant).
// ---------------------------------------------------------------------------
__global__ void __launch_bounds__(320, 3) edge_kernel(
    const float* __restrict__ natt, const int* __restrict__ edges,
    const float* __restrict__ edges_y, const float* __restrict__ rel_table,
    const float* __restrict__ ws, const float* __restrict__ fb,
    const float* __restrict__ out_w,
    float* __restrict__ out, int n_nodes)
{
    __shared__ __align__(16) float s_w[640];   // ws[512] | fb[64] | ow[64]
    __shared__ float s_logit[2][20];

    const int tid   = threadIdx.x;
    const int wid   = tid >> 5;            // 0..9
    const int lane  = tid & 31;
    const int seg_l = wid / 5;             // 0..1
    const int wis   = wid - seg_l * 5;     // 0..4

    const long long e_base = (long long)blockIdx.x * 40 + seg_l * 20 + wis * 4;

    int4 a = make_int4(0, 0, 0, 0);
    if (lane < 8)
        a = __ldg(&reinterpret_cast<const int4*>(edges)[2 * e_base + lane]);

    const int eg    = __shfl_sync(0xFFFFFFFFu, a.x, 0);
    const int vi    = __shfl_sync(0xFFFFFFFFu, a.y, 0);
    const int vj0   = __shfl_sync(0xFFFFFFFFu, a.z, 0);
    const int rel0  = __shfl_sync(0xFFFFFFFFu, a.w, 0);
    const int e2vi0 = __shfl_sync(0xFFFFFFFFu, a.z, 1);
    const int e2vj0 = __shfl_sync(0xFFFFFFFFu, a.w, 1);
    const int vj1   = __shfl_sync(0xFFFFFFFFu, a.z, 2);
    const int rel1  = __shfl_sync(0xFFFFFFFFu, a.w, 2);
    const int e2vi1 = __shfl_sync(0xFFFFFFFFu, a.z, 3);
    const int e2vj1 = __shfl_sync(0xFFFFFFFFu, a.w, 3);
    const int vj2   = __shfl_sync(0xFFFFFFFFu, a.z, 4);
    const int rel2  = __shfl_sync(0xFFFFFFFFu, a.w, 4);
    const int e2vi2 = __shfl_sync(0xFFFFFFFFu, a.z, 5);
    const int e2vj2 = __shfl_sync(0xFFFFFFFFu, a.w, 5);
    const int vj3   = __shfl_sync(0xFFFFFFFFu, a.z, 6);
    const int rel3  = __shfl_sync(0xFFFFFFFFu, a.w, 6);
    const int e2vi3 = __shfl_sync(0xFFFFFFFFu, a.z, 7);
    const int e2vj3 = __shfl_sync(0xFFFFFFFFu, a.w, 7);
    const int vjL   = __shfl_sync(0xFFFFFFFFu, a.z, 2 * (lane & 3));

    {
        int i = tid;
        s_w[i] = (i < 512) ? __ldg(&ws[i])
                           : (i < 576 ? __ldg(&fb[i - 512]) : __ldg(&out_w[i - 576]));
        int i2 = tid + 320;
        s_w[i2] = (i2 < 512) ? __ldg(&ws[i2])
                             : (i2 < 576 ? __ldg(&fb[i2 - 512]) : __ldg(&out_w[i2 - 576]));
    }

    const int d = 2 * lane;
    const float2 f0a = __ldg(reinterpret_cast<const float2*>(&g_hc[(size_t)e2vi0 * 64 + d]));
    const float2 f0b = __ldg(reinterpret_cast<const float2*>(&g_hc[(size_t)e2vi1 * 64 + d]));
    const float2 f0c = __ldg(reinterpret_cast<const float2*>(&g_hc[(size_t)e2vi2 * 64 + d]));
    const float2 f0d = __ldg(reinterpret_cast<const float2*>(&g_hc[(size_t)e2vi3 * 64 + d]));
    const float2 f3a = __ldg(reinterpret_cast<const float2*>(&g_hc[(size_t)e2vj0 * 64 + d]));
    const float2 f3b = __ldg(reinterpret_cast<const float2*>(&g_hc[(size_t)e2vj1 * 64 + d]));
    const float2 f3c = __ldg(reinterpret_cast<const float2*>(&g_hc[(size_t)e2vj2 * 64 + d]));
    const float2 f3d = __ldg(reinterpret_cast<const float2*>(&g_hc[(size_t)e2vj3 * 64 + d]));
    const float2 f4a = __ldg(reinterpret_cast<const float2*>(&g_hu[(size_t)vj0 * 64 + d]));
    const float2 f4b = __ldg(reinterpret_cast<const float2*>(&g_hu[(size_t)vj1 * 64 + d]));
    const float2 f4c = __ldg(reinterpret_cast<const float2*>(&g_hu[(size_t)vj2 * 64 + d]));
    const float2 f4d = __ldg(reinterpret_cast<const float2*>(&g_hu[(size_t)vj3 * 64 + d]));
    const float2 f2a = __ldg(reinterpret_cast<const float2*>(&rel_table[(size_t)rel0 * 64 + d]));
    const float2 f2b = __ldg(reinterpret_cast<const float2*>(&rel_table[(size_t)rel1 * 64 + d]));
    const float2 f2c = __ldg(reinterpret_cast<const float2*>(&rel_table[(size_t)rel2 * 64 + d]));
    const float2 f2d = __ldg(reinterpret_cast<const float2*>(&rel_table[(size_t)rel3 * 64 + d]));
    const float2 f1  = __ldg(reinterpret_cast<const float2*>(&g_hu[(size_t)vi * 64 + d]));
    const float att  = __ldg(&natt[(size_t)eg * n_nodes + vi]);
    const float ey   = (lane < 4) ? __ldg(&edges_y[e_base + lane]) : 0.0f;

    __syncthreads();

    const float2 w0 = *reinterpret_cast<const float2*>(&s_w[0 * 64 + d]);
    const float2 w1 = *reinterpret_cast<const float2*>(&s_w[1 * 64 + d]);
    const float2 w2 = *reinterpret_cast<const float2*>(&s_w[2 * 64 + d]);
    const float2 w3 = *reinterpret_cast<const float2*>(&s_w[3 * 64 + d]);
    const float2 w4 = *reinterpret_cast<const float2*>(&s_w[4 * 64 + d]);
    const float2 w5 = *reinterpret_cast<const float2*>(&s_w[5 * 64 + d]);
    const float2 w6 = *reinterpret_cast<const float2*>(&s_w[6 * 64 + d]);
    const float2 w7 = *reinterpret_cast<const float2*>(&s_w[7 * 64 + d]);
    const float2 vb = *reinterpret_cast<const float2*>(&s_w[512 + d]);
    const float2 ow = *reinterpret_cast<const float2*>(&s_w[576 + d]);

    const float h4x = f1.x * w4.x, h4y = f1.y * w4.y;
    const float h5x = f1.x * w5.x, h5y = f1.y * w5.y;
    const float h6x = f1.x * w6.x, h6y = f1.y * w6.y;
    const float h7x = f1.x * w7.x, h7y = f1.y * w7.y;

#define EDGE_LOGIT(f0v, f2v, f3v, f4v, lout)                                     \
    {                                                                            \
        float a1x = f0v.x * f2v.x, a1y = f0v.y * f2v.y;                          \
        float c3x = fmaf(f0v.x, w0.x, fmaf(a1x, w1.x, fmaf(f2v.x, h5x, h4x)));   \
        float c3y = fmaf(f0v.y, w0.y, fmaf(a1y, w1.y, fmaf(f2v.y, h5y, h4y)));   \
        float c4x = fmaf(f0v.x, w2.x, fmaf(a1x, w3.x, fmaf(f2v.x, h7x, h6x)));   \
        float c4y = fmaf(f0v.y, w2.y, fmaf(a1y, w3.y, fmaf(f2v.y, h7y, h6y)));   \
        float oxv = fmaf(f3v.x, c3x, fmaf(f4v.x, c4x, vb.x));                    \
        float oyv = fmaf(f3v.y, c3y, fmaf(f4v.y, c4y, vb.y));                    \
        lout = fmaf(fmaxf(oxv, 0.0f), ow.x, fmaxf(oyv, 0.0f) * ow.y);            \
    }

    float l0, l1, l2, l3;
    EDGE_LOGIT(f0a, f2a, f3a, f4a, l0)
    EDGE_LOGIT(f0b, f2b, f3b, f4b, l1)
    EDGE_LOGIT(f0c, f2c, f3c, f4c, l2)
    EDGE_LOGIT(f0d, f2d, f3d, f4d, l3)
#undef EDGE_LOGIT

#pragma unroll
    for (int s = 16; s > 0; s >>= 1) {
        l0 += __shfl_xor_sync(0xFFFFFFFFu, l0, s);
        l1 += __shfl_xor_sync(0xFFFFFFFFu, l1, s);
        l2 += __shfl_xor_sync(0xFFFFFFFFu, l2, s);
        l3 += __shfl_xor_sync(0xFFFFFFFFu, l3, s);
    }
    if (lane == 0) {
        s_logit[seg_l][wis * 4 + 0] = l0;
        s_logit[seg_l][wis * 4 + 1] = l1;
        s_logit[seg_l][wis * 4 + 2] = l2;
        s_logit[seg_l][wis * 4 + 3] = l3;
    }
    __syncthreads();

    float l = (lane < 20) ? s_logit[seg_l][lane] : -1e30f;
    float m = l;
#pragma unroll
    for (int s = 16; s > 0; s >>= 1) m = fmaxf(m, __shfl_xor_sync(0xFFFFFFFFu, m, s));
    float ev = (lane < 20) ? __expf(l - m) : 0.0f;
#pragma unroll
    for (int s = 16; s > 0; s >>= 1) ev += __shfl_xor_sync(0xFFFFFFFFu, ev, s);

    if (lane < 4) {
        float lg = s_logit[seg_l][wis * 4 + lane];
        float trans = __expf(lg - m) / ev;
        atomicAdd(&out[(size_t)eg * n_nodes + vjL], trans * att * ey);
    }
}

// ---------------------------------------------------------------------------
extern "C" void kernel_launch(void* const* d_in, const int* in_sizes, int n_in,
                              void* d_out, int out_size)
{
    const float* natt    = (const float*)d_in[0];
    const int*   edges   = (const int*)d_in[1];
    const float* edges_y = (const float*)d_in[2];
    const float* hu_in   = (const float*)d_in[3];   // [1, n_nodes, 256]
    const float* hc_in   = (const float*)d_in[4];   // [n_mem, 64]
    const float* Wc      = (const float*)d_in[5];
    const float* bc      = (const float*)d_in[6];
    const float* Wu      = (const float*)d_in[7];
    const float* bu      = (const float*)d_in[8];
    const float* rel_t   = (const float*)d_in[9];
    const float* ws      = (const float*)d_in[10];
    const float* fb      = (const float*)d_in[11];
    const float* ow      = (const float*)d_in[12];

    const int E       = in_sizes[2];
    const int n_nodes = in_sizes[3] / 256;
    const int n_mem   = in_sizes[4] / 64;
    const int n_seg   = E / 20;

    const int nb_c = (n_mem + 127) / 128;      // 1024
    const int nb_u = (n_nodes + 127) / 128;    // 391

    const int dyn_smem = 13312 * 4;            // 53,248 bytes
    cudaFuncSetAttribute(proj_both_kernel,
                         cudaFuncAttributeMaxDynamicSharedMemorySize, dyn_smem);
    cudaFuncSetAttribute(proj_both_kernel,
                         cudaFuncAttributePreferredSharedMemoryCarveout, 100);

    cudaMemsetAsync(d_out, 0, (size_t)out_size * sizeof(float));     // launch 1

    proj_both_kernel<<<nb_c + nb_u, 256, dyn_smem>>>(                // launch 2
        hc_in, Wc, bc, n_mem, hu_in, Wu, bu, n_nodes, nb_u);

    capture_align_kernel<<<1, 32>>>();                               // launch 3

    edge_kernel<<<n_seg / 2, 320>>>(natt, edges, edges_y, rel_t,     // launch 4
                                    ws, fb, ow, (float*)d_out, n_nodes);
}

// round 14
// speedup vs baseline: 1.1615x; 1.1615x over previous
#include <cuda_runtime.h>
#include <cstdint>

// ---------------------------------------------------------------------------
// Problem constants: B=4, E=400000, N_NODES=50000, N_REL=500, D=64, D_LG=256,
// K_PER_VI=20, N_MEM=131072. Scratch via device globals (no allocation).
// ---------------------------------------------------------------------------
__device__ float g_hc[131072 * 64];        // tanh(hidden_con @ Wc + bc)
__device__ float g_hu[50000 * 64];         // tanh(hidden_uncon @ Wu + bu), used rows only
__device__ unsigned char g_flags[50000];   // node used by edge kernel?
__device__ int g_list[50000];              // compacted used-node ids
__device__ int g_count;                    // number of used nodes

// ---------------- packed f32x2 helpers (sm_103a) ----------------
__device__ __forceinline__ void unpack2(unsigned long long u, float& x, float& y) {
    asm("mov.b64 {%0,%1}, %2;" : "=f"(x), "=f"(y) : "l"(u));
}
__device__ __forceinline__ unsigned long long dup2(float x) {
    unsigned long long u;
    asm("mov.b64 %0, {%1,%1};" : "=l"(u) : "f"(x));
    return u;
}
__device__ __forceinline__ void fma2(unsigned long long& d,
                                     unsigned long long a, unsigned long long b) {
    asm("fma.rn.f32x2 %0, %1, %2, %0;" : "+l"(d) : "l"(a), "l"(b));
}

__device__ __forceinline__ float tanh_fast(float x) {
    float e = __expf(-2.0f * fabsf(x));
    float t = (1.0f - e) / (1.0f + e);
    return copysignf(t, x);
}

// ---------------------------------------------------------------------------
// Node-usage flagging + compaction (hu is only read at rows {vi} U {vj};
// random draws cover ~55% of nodes, so ~45% of the hu GEMM is dead work).
// Compaction order is nondeterministic (atomicAdd) but each row's computed
// value is independent of order -> output deterministic.
// ---------------------------------------------------------------------------
__global__ void flag_kernel(const int* __restrict__ edges, int E) {
    int e = blockIdx.x * 256 + threadIdx.x;
    if (e < E) {
        int4 ra = __ldg(&reinterpret_cast<const int4*>(edges)[2 * (size_t)e]);
        g_flags[ra.y] = 1;   // vi
        g_flags[ra.z] = 1;   // vj
    }
}

__global__ void compact_kernel(int n) {
    int i = blockIdx.x * 256 + threadIdx.x;
    if (i < n && g_flags[i]) {
        int p = atomicAdd(&g_count, 1);
        g_list[p] = i;
    }
}

// ---------------------------------------------------------------------------
// Projection v10 = round-12 compute (2 rows x 16 cols/thread; cp.async
// double-buffered; float4 x-loads) + optional row indirection for hu.
// Block = 128 rows x 64 cols, 256 threads.
// Smem: Xbuf[128][36] x2 | Wbuf[32][64] x2 | s_nodes[128] = 53,760 B.
// ---------------------------------------------------------------------------
template <int K, bool IND>
__device__ __forceinline__ void proj_tile_async(
    const float* __restrict__ X, const float* __restrict__ W,
    const float* __restrict__ bias, float* __restrict__ out,
    int rows, int bid, float* sm, const int* __restrict__ list)
{
    constexpr int NC = K / 32;
    float* xbuf[2] = {sm, sm + 4608};
    float* wbuf[2] = {sm + 9216, sm + 11264};
    int* s_nodes = reinterpret_cast<int*>(sm + 13312);

    const int tid  = threadIdx.x;
    const int lane = tid & 31;
    const int warp = tid >> 5;
    const int cg   = lane >> 3;
    const int rp   = lane & 7;
    const int r0   = bid * 128;
    const int row0 = warp * 16 + rp;

    if (IND) {
        if (tid < 128) {
            int r = r0 + tid;
            s_nodes[tid] = (r < rows) ? __ldg(&list[r]) : 0;
        }
        __syncthreads();
    }

    unsigned int xs[2], wsm[2];
    xs[0]  = (unsigned int)__cvta_generic_to_shared(xbuf[0]);
    xs[1]  = (unsigned int)__cvta_generic_to_shared(xbuf[1]);
    wsm[0] = (unsigned int)__cvta_generic_to_shared(wbuf[0]);
    wsm[1] = (unsigned int)__cvta_generic_to_shared(wbuf[1]);

    auto issue_chunk = [&](int c) {
        const int k0 = c * 32;
        const unsigned int xdst = xs[c & 1];
        const unsigned int wdst = wsm[c & 1];
#pragma unroll
        for (int p = 0; p < 4; p++) {
            int idx = tid + p * 256;
            int row = idx >> 3, c16 = idx & 7;
            int grow = r0 + row;
            int sz = (grow < rows) ? 16 : 0;
            size_t srow;
            if (IND) {
                srow = (size_t)s_nodes[row];          // 0 for invalid (sz=0)
            } else {
                if (grow >= rows) grow = rows - 1;    // clamp; sz=0 reads none
                srow = (size_t)grow;
            }
            const float* src = X + srow * K + k0 + 4 * c16;
            unsigned int dst = xdst + (unsigned int)(row * 36 + 4 * c16) * 4u;
            asm volatile("cp.async.ca.shared.global [%0], [%1], 16, %2;"
                         :: "r"(dst), "l"(src), "r"(sz) : "memory");
        }
#pragma unroll
        for (int p = 0; p < 2; p++) {
            int idx = tid + p * 256;
            const float* src = W + (size_t)k0 * 64 + 4 * idx;
            unsigned int dst = wdst + (unsigned int)(4 * idx) * 4u;
            asm volatile("cp.async.ca.shared.global [%0], [%1], 16;"
                         :: "r"(dst), "l"(src) : "memory");
        }
        asm volatile("cp.async.commit_group;" ::: "memory");
    };

    unsigned long long acc[2][8];
#pragma unroll
    for (int r = 0; r < 2; r++)
#pragma unroll
        for (int j = 0; j < 8; j++) acc[r][j] = 0ull;

    issue_chunk(0);

#pragma unroll
    for (int c = 0; c < NC; c++) {
        if (c + 1 < NC) {
            issue_chunk(c + 1);
            asm volatile("cp.async.wait_group 1;" ::: "memory");
        } else {
            asm volatile("cp.async.wait_group 0;" ::: "memory");
        }
        __syncthreads();

        const float4* xb0 = reinterpret_cast<const float4*>(
                                xbuf[c & 1] + (size_t)row0 * 36);
        const float4* xb1 = reinterpret_cast<const float4*>(
                                xbuf[c & 1] + (size_t)(row0 + 8) * 36);
        const float* wb = wbuf[c & 1] + cg * 16;
#pragma unroll
        for (int k4 = 0; k4 < 8; k4++) {
            float4 xq0 = xb0[k4];
            float4 xq1 = xb1[k4];
            const float x0[4] = {xq0.x, xq0.y, xq0.z, xq0.w};
            const float x1[4] = {xq1.x, xq1.y, xq1.z, xq1.w};
#pragma unroll
            for (int t = 0; t < 4; t++) {
                unsigned long long d0 = dup2(x0[t]);
                unsigned long long d1 = dup2(x1[t]);
                const ulonglong2* wp = reinterpret_cast<const ulonglong2*>(
                    wb + (size_t)(4 * k4 + t) * 64);
                ulonglong2 wA = wp[0], wB = wp[1], wC = wp[2], wD = wp[3];
                unsigned long long wv[8] = {wA.x, wA.y, wB.x, wB.y,
                                            wC.x, wC.y, wD.x, wD.y};
#pragma unroll
                for (int j = 0; j < 8; j++) fma2(acc[0][j], d0, wv[j]);
#pragma unroll
                for (int j = 0; j < 8; j++) fma2(acc[1][j], d1, wv[j]);
            }
        }
        __syncthreads();
    }

    // ---- epilogue: bias + tanh, stage to smem [128][68], coalesced stores --
    float bv[16];
#pragma unroll
    for (int j = 0; j < 16; j++) bv[j] = __ldg(&bias[cg * 16 + j]);
#pragma unroll
    for (int r = 0; r < 2; r++) {
        int row = row0 + 8 * r;
        float* dst = &sm[(size_t)row * 68 + cg * 16];
#pragma unroll
        for (int j = 0; j < 8; j++) {
            float a, b;
            unpack2(acc[r][j], a, b);
            *reinterpret_cast<float2*>(dst + 2 * j) =
                make_float2(tanh_fast(a + bv[2 * j]), tanh_fast(b + bv[2 * j + 1]));
        }
    }
    __syncthreads();
#pragma unroll
    for (int i = 0; i < 8; i++) {
        int idx = tid + i * 256;
        int row = idx >> 4, c4 = idx & 15;
        int grow = r0 + row;
        if (grow < rows) {
            size_t orow = IND ? (size_t)s_nodes[row] : (size_t)grow;
            *reinterpret_cast<float4*>(&out[orow * 64 + 4 * c4]) =
                *reinterpret_cast<const float4*>(&sm[(size_t)row * 68 + 4 * c4]);
        }
    }
}

__global__ void __launch_bounds__(256, 3) proj_both_kernel(
    const float* __restrict__ Xc, const float* __restrict__ Wc,
    const float* __restrict__ bc, int rows_c,
    const float* __restrict__ Xu, const float* __restrict__ Wu,
    const float* __restrict__ bu, int nb_u)
{
    extern __shared__ float sm[];
    if ((int)blockIdx.x < nb_u) {
        int cnt = g_count;                       // written by compact_kernel
        if ((int)blockIdx.x * 128 >= cnt) return;   // surplus hu blocks exit
        proj_tile_async<256, true>(Xu, Wu, bu, g_hu, cnt, blockIdx.x, sm, g_list);
    } else {
        proj_tile_async<64, false>(Xc, Wc, bc, g_hc, rows_c,
                                   blockIdx.x - nb_u, sm, nullptr);
    }
}

// ---------------------------------------------------------------------------
// Edge kernel v4 (known 64us): 2 segments per 320-thread block, 5 warps/
// segment, 4 edges/warp. Weights staged in smem once per block; gathers
// front-batched; out_b dropped (softmax-invariant).
// ---------------------------------------------------------------------------
__global__ void __launch_bounds__(320, 3) edge_kernel(
    const float* __restrict__ natt, const int* __restrict__ edges,
    const float* __restrict__ edges_y, const float* __restrict__ rel_table,
    const float* __restrict__ ws, const float* __restrict__ fb,
    const float* __restrict__ out_w,
    float* __restrict__ out, int n_nodes)
{
    __shared__ __align__(16) float s_w[640];   // ws[512] | fb[64] | ow[64]
    __shared__ float s_logit[2][20];

    const int tid   = threadIdx.x;
    const int wid   = tid >> 5;            // 0..9
    const int lane  = tid & 31;
    const int seg_l = wid / 5;             // 0..1
    const int wis   = wid - seg_l * 5;     // 0..4

    const long long e_base = (long long)blockIdx.x * 40 + seg_l * 20 + wis * 4;

    int4 a = make_int4(0, 0, 0, 0);
    if (lane < 8)
        a = __ldg(&reinterpret_cast<const int4*>(edges)[2 * e_base + lane]);

    const int eg    = __shfl_sync(0xFFFFFFFFu, a.x, 0);
    const int vi    = __shfl_sync(0xFFFFFFFFu, a.y, 0);
    const int vj0   = __shfl_sync(0xFFFFFFFFu, a.z, 0);
    const int rel0  = __shfl_sync(0xFFFFFFFFu, a.w, 0);
    const int e2vi0 = __shfl_sync(0xFFFFFFFFu, a.z, 1);
    const int e2vj0 = __shfl_sync(0xFFFFFFFFu, a.w, 1);
    const int vj1   = __shfl_sync(0xFFFFFFFFu, a.z, 2);
    const int rel1  = __shfl_sync(0xFFFFFFFFu, a.w, 2);
    const int e2vi1 = __shfl_sync(0xFFFFFFFFu, a.z, 3);
    const int e2vj1 = __shfl_sync(0xFFFFFFFFu, a.w, 3);
    const int vj2   = __shfl_sync(0xFFFFFFFFu, a.z, 4);
    const int rel2  = __shfl_sync(0xFFFFFFFFu, a.w, 4);
    const int e2vi2 = __shfl_sync(0xFFFFFFFFu, a.z, 5);
    const int e2vj2 = __shfl_sync(0xFFFFFFFFu, a.w, 5);
    const int vj3   = __shfl_sync(0xFFFFFFFFu, a.z, 6);
    const int rel3  = __shfl_sync(0xFFFFFFFFu, a.w, 6);
    const int e2vi3 = __shfl_sync(0xFFFFFFFFu, a.z, 7);
    const int e2vj3 = __shfl_sync(0xFFFFFFFFu, a.w, 7);
    const int vjL   = __shfl_sync(0xFFFFFFFFu, a.z, 2 * (lane & 3));

    {
        int i = tid;
        s_w[i] = (i < 512) ? __ldg(&ws[i])
                           : (i < 576 ? __ldg(&fb[i - 512]) : __ldg(&out_w[i - 576]));
        int i2 = tid + 320;
        s_w[i2] = (i2 < 512) ? __ldg(&ws[i2])
                             : (i2 < 576 ? __ldg(&fb[i2 - 512]) : __ldg(&out_w[i2 - 576]));
    }

    const int d = 2 * lane;
    const float2 f0a = __ldg(reinterpret_cast<const float2*>(&g_hc[(size_t)e2vi0 * 64 + d]));
    const float2 f0b = __ldg(reinterpret_cast<const float2*>(&g_hc[(size_t)e2vi1 * 64 + d]));
    const float2 f0c = __ldg(reinterpret_cast<const float2*>(&g_hc[(size_t)e2vi2 * 64 + d]));
    const float2 f0d = __ldg(reinterpret_cast<const float2*>(&g_hc[(size_t)e2vi3 * 64 + d]));
    const float2 f3a = __ldg(reinterpret_cast<const float2*>(&g_hc[(size_t)e2vj0 * 64 + d]));
    const float2 f3b = __ldg(reinterpret_cast<const float2*>(&g_hc[(size_t)e2vj1 * 64 + d]));
    const float2 f3c = __ldg(reinterpret_cast<const float2*>(&g_hc[(size_t)e2vj2 * 64 + d]));
    const float2 f3d = __ldg(reinterpret_cast<const float2*>(&g_hc[(size_t)e2vj3 * 64 + d]));
    const float2 f4a = __ldg(reinterpret_cast<const float2*>(&g_hu[(size_t)vj0 * 64 + d]));
    const float2 f4b = __ldg(reinterpret_cast<const float2*>(&g_hu[(size_t)vj1 * 64 + d]));
    const float2 f4c = __ldg(reinterpret_cast<const float2*>(&g_hu[(size_t)vj2 * 64 + d]));
    const float2 f4d = __ldg(reinterpret_cast<const float2*>(&g_hu[(size_t)vj3 * 64 + d]));
    const float2 f2a = __ldg(reinterpret_cast<const float2*>(&rel_table[(size_t)rel0 * 64 + d]));
    const float2 f2b = __ldg(reinterpret_cast<const float2*>(&rel_table[(size_t)rel1 * 64 + d]));
    const float2 f2c = __ldg(reinterpret_cast<const float2*>(&rel_table[(size_t)rel2 * 64 + d]));
    const float2 f2d = __ldg(reinterpret_cast<const float2*>(&rel_table[(size_t)rel3 * 64 + d]));
    const float2 f1  = __ldg(reinterpret_cast<const float2*>(&g_hu[(size_t)vi * 64 + d]));
    const float att  = __ldg(&natt[(size_t)eg * n_nodes + vi]);
    const float ey   = (lane < 4) ? __ldg(&edges_y[e_base + lane]) : 0.0f;

    __syncthreads();

    const float2 w0 = *reinterpret_cast<const float2*>(&s_w[0 * 64 + d]);
    const float2 w1 = *reinterpret_cast<const float2*>(&s_w[1 * 64 + d]);
    const float2 w2 = *reinterpret_cast<const float2*>(&s_w[2 * 64 + d]);
    const float2 w3 = *reinterpret_cast<const float2*>(&s_w[3 * 64 + d]);
    const float2 w4 = *reinterpret_cast<const float2*>(&s_w[4 * 64 + d]);
    const float2 w5 = *reinterpret_cast<const float2*>(&s_w[5 * 64 + d]);
    const float2 w6 = *reinterpret_cast<const float2*>(&s_w[6 * 64 + d]);
    const float2 w7 = *reinterpret_cast<const float2*>(&s_w[7 * 64 + d]);
    const float2 vb = *reinterpret_cast<const float2*>(&s_w[512 + d]);
    const float2 ow = *reinterpret_cast<const float2*>(&s_w[576 + d]);

    const float h4x = f1.x * w4.x, h4y = f1.y * w4.y;
    const float h5x = f1.x * w5.x, h5y = f1.y * w5.y;
    const float h6x = f1.x * w6.x, h6y = f1.y * w6.y;
    const float h7x = f1.x * w7.x, h7y = f1.y * w7.y;

#define EDGE_LOGIT(f0v, f2v, f3v, f4v, lout)                                     \
    {                                                                            \
        float a1x = f0v.x * f2v.x, a1y = f0v.y * f2v.y;                          \
        float c3x = fmaf(f0v.x, w0.x, fmaf(a1x, w1.x, fmaf(f2v.x, h5x, h4x)));   \
        float c3y = fmaf(f0v.y, w0.y, fmaf(a1y, w1.y, fmaf(f2v.y, h5y, h4y)));   \
        float c4x = fmaf(f0v.x, w2.x, fmaf(a1x, w3.x, fmaf(f2v.x, h7x, h6x)));   \
        float c4y = fmaf(f0v.y, w2.y, fmaf(a1y, w3.y, fmaf(f2v.y, h7y, h6y)));   \
        float oxv = fmaf(f3v.x, c3x, fmaf(f4v.x, c4x, vb.x));                    \
        float oyv = fmaf(f3v.y, c3y, fmaf(f4v.y, c4y, vb.y));                    \
        lout = fmaf(fmaxf(oxv, 0.0f), ow.x, fmaxf(oyv, 0.0f) * ow.y);            \
    }

    float l0, l1, l2, l3;
    EDGE_LOGIT(f0a, f2a, f3a, f4a, l0)
    EDGE_LOGIT(f0b, f2b, f3b, f4b, l1)
    EDGE_LOGIT(f0c, f2c, f3c, f4c, l2)
    EDGE_LOGIT(f0d, f2d, f3d, f4d, l3)
#undef EDGE_LOGIT

#pragma unroll
    for (int s = 16; s > 0; s >>= 1) {
        l0 += __shfl_xor_sync(0xFFFFFFFFu, l0, s);
        l1 += __shfl_xor_sync(0xFFFFFFFFu, l1, s);
        l2 += __shfl_xor_sync(0xFFFFFFFFu, l2, s);
        l3 += __shfl_xor_sync(0xFFFFFFFFu, l3, s);
    }
    if (lane == 0) {
        s_logit[seg_l][wis * 4 + 0] = l0;
        s_logit[seg_l][wis * 4 + 1] = l1;
        s_logit[seg_l][wis * 4 + 2] = l2;
        s_logit[seg_l][wis * 4 + 3] = l3;
    }
    __syncthreads();

    float l = (lane < 20) ? s_logit[seg_l][lane] : -1e30f;
    float m = l;
#pragma unroll
    for (int s = 16; s > 0; s >>= 1) m = fmaxf(m, __shfl_xor_sync(0xFFFFFFFFu, m, s));
    float ev = (lane < 20) ? __expf(l - m) : 0.0f;
#pragma unroll
    for (int s = 16; s > 0; s >>= 1) ev += __shfl_xor_sync(0xFFFFFFFFu, ev, s);

    if (lane < 4) {
        float lg = s_logit[seg_l][wis * 4 + lane];
        float trans = __expf(lg - m) / ev;
        atomicAdd(&out[(size_t)eg * n_nodes + vjL], trans * att * ey);
    }
}

// ---------------------------------------------------------------------------
extern "C" void kernel_launch(void* const* d_in, const int* in_sizes, int n_in,
                              void* d_out, int out_size)
{
    const float* natt    = (const float*)d_in[0];
    const int*   edges   = (const int*)d_in[1];
    const float* edges_y = (const float*)d_in[2];
    const float* hu_in   = (const float*)d_in[3];   // [1, n_nodes, 256]
    const float* hc_in   = (const float*)d_in[4];   // [n_mem, 64]
    const float* Wc      = (const float*)d_in[5];
    const float* bc      = (const float*)d_in[6];
    const float* Wu      = (const float*)d_in[7];
    const float* bu      = (const float*)d_in[8];
    const float* rel_t   = (const float*)d_in[9];
    const float* ws      = (const float*)d_in[10];
    const float* fb      = (const float*)d_in[11];
    const float* ow      = (const float*)d_in[12];

    const int E       = in_sizes[2];
    const int n_nodes = in_sizes[3] / 256;
    const int n_mem   = in_sizes[4] / 64;
    const int n_seg   = E / 20;

    const int nb_c = (n_mem + 127) / 128;      // 1024
    const int nb_u = (n_nodes + 127) / 128;    // 391 (upper bound for hu blocks)

    void* flags_ptr; cudaGetSymbolAddress(&flags_ptr, g_flags);
    void* count_ptr; cudaGetSymbolAddress(&count_ptr, g_count);

    const int dyn_smem = 13440 * 4;            // 53,760 bytes
    cudaFuncSetAttribute(proj_both_kernel,
                         cudaFuncAttributeMaxDynamicSharedMemorySize, dyn_smem);
    cudaFuncSetAttribute(proj_both_kernel,
                         cudaFuncAttributePreferredSharedMemoryCarveout, 100);

    cudaMemsetAsync(d_out, 0, (size_t)out_size * sizeof(float));     // launch 1
    cudaMemsetAsync(flags_ptr, 0, (size_t)n_nodes);                  // launch 2
    cudaMemsetAsync(count_ptr, 0, sizeof(int));                      // launch 3

    flag_kernel<<<(E + 255) / 256, 256>>>(edges, E);                 // launch 4
    compact_kernel<<<(n_nodes + 255) / 256, 256>>>(n_nodes);         // launch 5

    proj_both_kernel<<<nb_u + nb_c, 256, dyn_smem>>>(                // launch 6
        hc_in, Wc, bc, n_mem, hu_in, Wu, bu, nb_u);

    edge_kernel<<<n_seg / 2, 320>>>(natt, edges, edges_y, rel_t,     // launch 7
                                    ws, fb, ow, (float*)d_out, n_nodes);
}

// round 15
// speedup vs baseline: 1.2101x; 1.0418x over previous
#include <cuda_runtime.h>
#include <cstdint>

// ---------------------------------------------------------------------------
// Problem constants: B=4, E=400000, N_NODES=50000, N_REL=500, D=64, D_LG=256,
// K_PER_VI=20, N_MEM=131072. Scratch via device globals (no allocation).
// ---------------------------------------------------------------------------
__device__ float g_hc[131072 * 64];   // tanh(hidden_con @ Wc + bc)
__device__ float g_hu[50000 * 64];    // tanh(hidden_uncon @ Wu + bu)

// ---------------- packed f32x2 helpers (sm_103a) ----------------
__device__ __forceinline__ void unpack2(unsigned long long u, float& x, float& y) {
    asm("mov.b64 {%0,%1}, %2;" : "=f"(x), "=f"(y) : "l"(u));
}
__device__ __forceinline__ unsigned long long dup2(float x) {
    unsigned long long u;
    asm("mov.b64 %0, {%1,%1};" : "=l"(u) : "f"(x));
    return u;
}
__device__ __forceinline__ void fma2(unsigned long long& d,
                                     unsigned long long a, unsigned long long b) {
    asm("fma.rn.f32x2 %0, %1, %2, %0;" : "+l"(d) : "l"(a), "l"(b));
}

__device__ __forceinline__ float tanh_fast(float x) {
    float e = __expf(-2.0f * fabsf(x));
    float t = (1.0f - e) / (1.0f + e);
    return copysignf(t, x);
}

// ---------------------------------------------------------------------------
// Projection v11 = round-12 kernel with BANK-DECONFLICTED W smem layout.
//
// Round-12 W reads (row stride 64, groups at float offsets {0,16,32,48}) put
// cg0/cg2 on banks 0-3 and cg1/cg3 on banks 16-19 -> every W LDS.128 was 2
// wavefronts (measured L1tex 71%). New layout: W chunk stored [32][80], col
// group g at kk*80 + g*20 -> group banks {0-3,20-23,8-11,28-31} (1st 16B) and
// {4-7,24-27,12-15,0-3} (2nd 16B): conflict-free, halving W wavefronts.
// cp.async 16B chunks land wholly inside a 16-float group, so staging works.
//
// Thread tile 2 rows x 16 cols; cp.async double-buffered X[128][36] + W[32][80].
// Smem: 2*4608 + 2*2560 = 14336 floats = 57,344 B; 3 blocks/SM.
// ---------------------------------------------------------------------------
template <int K>
__device__ __forceinline__ void proj_tile_async(
    const float* __restrict__ X, const float* __restrict__ W,
    const float* __restrict__ bias, float* __restrict__ out,
    int rows, int bid, float* sm)
{
    constexpr int NC = K / 32;
    float* xbuf[2] = {sm, sm + 4608};
    float* wbuf[2] = {sm + 9216, sm + 11776};   // 32*80 = 2560 floats each

    const int tid  = threadIdx.x;
    const int lane = tid & 31;
    const int warp = tid >> 5;
    const int cg   = lane >> 3;           // 0..3: 16-col group
    const int rp   = lane & 7;
    const int r0   = bid * 128;
    const int row0 = warp * 16 + rp;      // rows row0, row0+8

    unsigned int xs[2], wsm[2];
    xs[0]  = (unsigned int)__cvta_generic_to_shared(xbuf[0]);
    xs[1]  = (unsigned int)__cvta_generic_to_shared(xbuf[1]);
    wsm[0] = (unsigned int)__cvta_generic_to_shared(wbuf[0]);
    wsm[1] = (unsigned int)__cvta_generic_to_shared(wbuf[1]);

    auto issue_chunk = [&](int c) {
        const int k0 = c * 32;
        const unsigned int xdst = xs[c & 1];
        const unsigned int wdst = wsm[c & 1];
#pragma unroll
        for (int p = 0; p < 4; p++) {
            int idx = tid + p * 256;            // 0..1023 16B chunks
            int row = idx >> 3, c16 = idx & 7;
            int grow = r0 + row;
            int sz = (grow < rows) ? 16 : 0;
            if (grow >= rows) grow = rows - 1;  // clamp; sz=0 reads none
            const float* src = X + (size_t)grow * K + k0 + 4 * c16;
            unsigned int dst = xdst + (unsigned int)(row * 36 + 4 * c16) * 4u;
            asm volatile("cp.async.ca.shared.global [%0], [%1], 16, %2;"
                         :: "r"(dst), "l"(src), "r"(sz) : "memory");
        }
#pragma unroll
        for (int p = 0; p < 2; p++) {
            int idx = tid + p * 256;            // 0..511 16B chunks
            int kk = idx >> 4;                  // W row (16 chunks per row)
            int g  = (idx >> 2) & 3;            // 16-float col group
            int w4 = idx & 3;                   // 16B chunk within group
            const float* src = W + (size_t)(k0 + kk) * 64 + g * 16 + 4 * w4;
            unsigned int dst =
                wdst + (unsigned int)(kk * 80 + g * 20 + 4 * w4) * 4u;
            asm volatile("cp.async.ca.shared.global [%0], [%1], 16;"
                         :: "r"(dst), "l"(src) : "memory");
        }
        asm volatile("cp.async.commit_group;" ::: "memory");
    };

    unsigned long long acc[2][8];
#pragma unroll
    for (int r = 0; r < 2; r++)
#pragma unroll
        for (int j = 0; j < 8; j++) acc[r][j] = 0ull;

    issue_chunk(0);

#pragma unroll
    for (int c = 0; c < NC; c++) {
        if (c + 1 < NC) {
            issue_chunk(c + 1);
            asm volatile("cp.async.wait_group 1;" ::: "memory");
        } else {
            asm volatile("cp.async.wait_group 0;" ::: "memory");
        }
        __syncthreads();

        const float4* xb0 = reinterpret_cast<const float4*>(
                                xbuf[c & 1] + (size_t)row0 * 36);
        const float4* xb1 = reinterpret_cast<const float4*>(
                                xbuf[c & 1] + (size_t)(row0 + 8) * 36);
        const float* wb = wbuf[c & 1] + cg * 20;
#pragma unroll
        for (int k4 = 0; k4 < 8; k4++) {
            float4 xq0 = xb0[k4];
            float4 xq1 = xb1[k4];
            const float x0[4] = {xq0.x, xq0.y, xq0.z, xq0.w};
            const float x1[4] = {xq1.x, xq1.y, xq1.z, xq1.w};
#pragma unroll
            for (int t = 0; t < 4; t++) {
                unsigned long long d0 = dup2(x0[t]);
                unsigned long long d1 = dup2(x1[t]);
                const ulonglong2* wp = reinterpret_cast<const ulonglong2*>(
                    wb + (size_t)(4 * k4 + t) * 80);
                ulonglong2 wA = wp[0], wB = wp[1];
                unsigned long long wv[4] = {wA.x, wA.y, wB.x, wB.y};
#pragma unroll
                for (int j = 0; j < 4; j++) fma2(acc[0][j], d0, wv[j]);
#pragma unroll
                for (int j = 0; j < 4; j++) fma2(acc[1][j], d1, wv[j]);
                // second 16B of the group (floats 8..15 of the 16-col tile)
                const ulonglong2* wq = wp + 2;   // floats +8..+15
                ulonglong2 wC = wq[0], wD = wq[1];
                unsigned long long wv2[4] = {wC.x, wC.y, wD.x, wD.y};
#pragma unroll
                for (int j = 0; j < 4; j++) fma2(acc[0][4 + j], d0, wv2[j]);
#pragma unroll
                for (int j = 0; j < 4; j++) fma2(acc[1][4 + j], d1, wv2[j]);
            }
        }
        __syncthreads();
    }

    // ---- epilogue: bias + tanh, stage to smem [128][68], coalesced stores --
    float bv[16];
#pragma unroll
    for (int j = 0; j < 16; j++) bv[j] = __ldg(&bias[cg * 16 + j]);
#pragma unroll
    for (int r = 0; r < 2; r++) {
        int row = row0 + 8 * r;
        float* dst = &sm[(size_t)row * 68 + cg * 16];
#pragma unroll
        for (int j = 0; j < 8; j++) {
            float a, b;
            unpack2(acc[r][j], a, b);
            *reinterpret_cast<float2*>(dst + 2 * j) =
                make_float2(tanh_fast(a + bv[2 * j]), tanh_fast(b + bv[2 * j + 1]));
        }
    }
    __syncthreads();
#pragma unroll
    for (int i = 0; i < 8; i++) {
        int idx = tid + i * 256;
        int row = idx >> 4, c4 = idx & 15;
        if (r0 + row < rows)
            *reinterpret_cast<float4*>(&out[(size_t)(r0 + row) * 64 + 4 * c4]) =
                *reinterpret_cast<const float4*>(&sm[(size_t)row * 68 + 4 * c4]);
    }
}

__global__ void __launch_bounds__(256, 3) proj_both_kernel(
    const float* __restrict__ Xc, const float* __restrict__ Wc,
    const float* __restrict__ bc, int rows_c,
    const float* __restrict__ Xu, const float* __restrict__ Wu,
    const float* __restrict__ bu, int rows_u, int nb_u)
{
    extern __shared__ float sm[];
    // heavy hu (K=256) blocks first: light hc blocks form the tail
    if ((int)blockIdx.x < nb_u) {
        proj_tile_async<256>(Xu, Wu, bu, g_hu, rows_u, blockIdx.x, sm);
    } else {
        proj_tile_async<64>(Xc, Wc, bc, g_hc, rows_c, blockIdx.x - nb_u, sm);
    }
}

// Tiny no-op kernel: keeps ncu's "-s 5 -c 1" capture landing on proj.
__global__ void capture_align_kernel() {}

// ---------------------------------------------------------------------------
// Edge kernel v4 (known 64us): 2 segments per 320-thread block, 5 warps/
// segment, 4 edges/warp. Weights staged in smem once per block; gathers
// front-batched; out_b dropped (softmax-invariant).
// ---------------------------------------------------------------------------
__global__ void __launch_bounds__(320, 3) edge_kernel(
    const float* __restrict__ natt, const int* __restrict__ edges,
    const float* __restrict__ edges_y, const float* __restrict__ rel_table,
    const float* __restrict__ ws, const float* __restrict__ fb,
    const float* __restrict__ out_w,
    float* __restrict__ out, int n_nodes)
{
    __shared__ __align__(16) float s_w[640];   // ws[512] | fb[64] | ow[64]
    __shared__ float s_logit[2][20];

    const int tid   = threadIdx.x;
    const int wid   = tid >> 5;            // 0..9
    const int lane  = tid & 31;
    const int seg_l = wid / 5;             // 0..1
    const int wis   = wid - seg_l * 5;     // 0..4

    const long long e_base = (long long)blockIdx.x * 40 + seg_l * 20 + wis * 4;

    int4 a = make_int4(0, 0, 0, 0);
    if (lane < 8)
        a = __ldg(&reinterpret_cast<const int4*>(edges)[2 * e_base + lane]);

    const int eg    = __shfl_sync(0xFFFFFFFFu, a.x, 0);
    const int vi    = __shfl_sync(0xFFFFFFFFu, a.y, 0);
    const int vj0   = __shfl_sync(0xFFFFFFFFu, a.z, 0);
    const int rel0  = __shfl_sync(0xFFFFFFFFu, a.w, 0);
    const int e2vi0 = __shfl_sync(0xFFFFFFFFu, a.z, 1);
    const int e2vj0 = __shfl_sync(0xFFFFFFFFu, a.w, 1);
    const int vj1   = __shfl_sync(0xFFFFFFFFu, a.z, 2);
    const int rel1  = __shfl_sync(0xFFFFFFFFu, a.w, 2);
    const int e2vi1 = __shfl_sync(0xFFFFFFFFu, a.z, 3);
    const int e2vj1 = __shfl_sync(0xFFFFFFFFu, a.w, 3);
    const int vj2   = __shfl_sync(0xFFFFFFFFu, a.z, 4);
    const int rel2  = __shfl_sync(0xFFFFFFFFu, a.w, 4);
    const int e2vi2 = __shfl_sync(0xFFFFFFFFu, a.z, 5);
    const int e2vj2 = __shfl_sync(0xFFFFFFFFu, a.w, 5);
    const int vj3   = __shfl_sync(0xFFFFFFFFu, a.z, 6);
    const int rel3  = __shfl_sync(0xFFFFFFFFu, a.w, 6);
    const int e2vi3 = __shfl_sync(0xFFFFFFFFu, a.z, 7);
    const int e2vj3 = __shfl_sync(0xFFFFFFFFu, a.w, 7);
    const int vjL   = __shfl_sync(0xFFFFFFFFu, a.z, 2 * (lane & 3));

    {
        int i = tid;
        s_w[i] = (i < 512) ? __ldg(&ws[i])
                           : (i < 576 ? __ldg(&fb[i - 512]) : __ldg(&out_w[i - 576]));
        int i2 = tid + 320;
        s_w[i2] = (i2 < 512) ? __ldg(&ws[i2])
                             : (i2 < 576 ? __ldg(&fb[i2 - 512]) : __ldg(&out_w[i2 - 576]));
    }

    const int d = 2 * lane;
    const float2 f0a = __ldg(reinterpret_cast<const float2*>(&g_hc[(size_t)e2vi0 * 64 + d]));
    const float2 f0b = __ldg(reinterpret_cast<const float2*>(&g_hc[(size_t)e2vi1 * 64 + d]));
    const float2 f0c = __ldg(reinterpret_cast<const float2*>(&g_hc[(size_t)e2vi2 * 64 + d]));
    const float2 f0d = __ldg(reinterpret_cast<const float2*>(&g_hc[(size_t)e2vi3 * 64 + d]));
    const float2 f3a = __ldg(reinterpret_cast<const float2*>(&g_hc[(size_t)e2vj0 * 64 + d]));
    const float2 f3b = __ldg(reinterpret_cast<const float2*>(&g_hc[(size_t)e2vj1 * 64 + d]));
    const float2 f3c = __ldg(reinterpret_cast<const float2*>(&g_hc[(size_t)e2vj2 * 64 + d]));
    const float2 f3d = __ldg(reinterpret_cast<const float2*>(&g_hc[(size_t)e2vj3 * 64 + d]));
    const float2 f4a = __ldg(reinterpret_cast<const float2*>(&g_hu[(size_t)vj0 * 64 + d]));
    const float2 f4b = __ldg(reinterpret_cast<const float2*>(&g_hu[(size_t)vj1 * 64 + d]));
    const float2 f4c = __ldg(reinterpret_cast<const float2*>(&g_hu[(size_t)vj2 * 64 + d]));
    const float2 f4d = __ldg(reinterpret_cast<const float2*>(&g_hu[(size_t)vj3 * 64 + d]));
    const float2 f2a = __ldg(reinterpret_cast<const float2*>(&rel_table[(size_t)rel0 * 64 + d]));
    const float2 f2b = __ldg(reinterpret_cast<const float2*>(&rel_table[(size_t)rel1 * 64 + d]));
    const float2 f2c = __ldg(reinterpret_cast<const float2*>(&rel_table[(size_t)rel2 * 64 + d]));
    const float2 f2d = __ldg(reinterpret_cast<const float2*>(&rel_table[(size_t)rel3 * 64 + d]));
    const float2 f1  = __ldg(reinterpret_cast<const float2*>(&g_hu[(size_t)vi * 64 + d]));
    const float att  = __ldg(&natt[(size_t)eg * n_nodes + vi]);
    const float ey   = (lane < 4) ? __ldg(&edges_y[e_base + lane]) : 0.0f;

    __syncthreads();

    const float2 w0 = *reinterpret_cast<const float2*>(&s_w[0 * 64 + d]);
    const float2 w1 = *reinterpret_cast<const float2*>(&s_w[1 * 64 + d]);
    const float2 w2 = *reinterpret_cast<const float2*>(&s_w[2 * 64 + d]);
    const float2 w3 = *reinterpret_cast<const float2*>(&s_w[3 * 64 + d]);
    const float2 w4 = *reinterpret_cast<const float2*>(&s_w[4 * 64 + d]);
    const float2 w5 = *reinterpret_cast<const float2*>(&s_w[5 * 64 + d]);
    const float2 w6 = *reinterpret_cast<const float2*>(&s_w[6 * 64 + d]);
    const float2 w7 = *reinterpret_cast<const float2*>(&s_w[7 * 64 + d]);
    const float2 vb = *reinterpret_cast<const float2*>(&s_w[512 + d]);
    const float2 ow = *reinterpret_cast<const float2*>(&s_w[576 + d]);

    const float h4x = f1.x * w4.x, h4y = f1.y * w4.y;
    const float h5x = f1.x * w5.x, h5y = f1.y * w5.y;
    const float h6x = f1.x * w6.x, h6y = f1.y * w6.y;
    const float h7x = f1.x * w7.x, h7y = f1.y * w7.y;

#define EDGE_LOGIT(f0v, f2v, f3v, f4v, lout)                                     \
    {                                                                            \
        float a1x = f0v.x * f2v.x, a1y = f0v.y * f2v.y;                          \
        float c3x = fmaf(f0v.x, w0.x, fmaf(a1x, w1.x, fmaf(f2v.x, h5x, h4x)));   \
        float c3y = fmaf(f0v.y, w0.y, fmaf(a1y, w1.y, fmaf(f2v.y, h5y, h4y)));   \
        float c4x = fmaf(f0v.x, w2.x, fmaf(a1x, w3.x, fmaf(f2v.x, h7x, h6x)));   \
        float c4y = fmaf(f0v.y, w2.y, fmaf(a1y, w3.y, fmaf(f2v.y, h7y, h6y)));   \
        float oxv = fmaf(f3v.x, c3x, fmaf(f4v.x, c4x, vb.x));                    \
        float oyv = fmaf(f3v.y, c3y, fmaf(f4v.y, c4y, vb.y));                    \
        lout = fmaf(fmaxf(oxv, 0.0f), ow.x, fmaxf(oyv, 0.0f) * ow.y);            \
    }

    float l0, l1, l2, l3;
    EDGE_LOGIT(f0a, f2a, f3a, f4a, l0)
    EDGE_LOGIT(f0b, f2b, f3b, f4b, l1)
    EDGE_LOGIT(f0c, f2c, f3c, f4c, l2)
    EDGE_LOGIT(f0d, f2d, f3d, f4d, l3)
#undef EDGE_LOGIT

#pragma unroll
    for (int s = 16; s > 0; s >>= 1) {
        l0 += __shfl_xor_sync(0xFFFFFFFFu, l0, s);
        l1 += __shfl_xor_sync(0xFFFFFFFFu, l1, s);
        l2 += __shfl_xor_sync(0xFFFFFFFFu, l2, s);
        l3 += __shfl_xor_sync(0xFFFFFFFFu, l3, s);
    }
    if (lane == 0) {
        s_logit[seg_l][wis * 4 + 0] = l0;
        s_logit[seg_l][wis * 4 + 1] = l1;
        s_logit[seg_l][wis * 4 + 2] = l2;
        s_logit[seg_l][wis * 4 + 3] = l3;
    }
    __syncthreads();

    float l = (lane < 20) ? s_logit[seg_l][lane] : -1e30f;
    float m = l;
#pragma unroll
    for (int s = 16; s > 0; s >>= 1) m = fmaxf(m, __shfl_xor_sync(0xFFFFFFFFu, m, s));
    float ev = (lane < 20) ? __expf(l - m) : 0.0f;
#pragma unroll
    for (int s = 16; s > 0; s >>= 1) ev += __shfl_xor_sync(0xFFFFFFFFu, ev, s);

    if (lane < 4) {
        float lg = s_logit[seg_l][wis * 4 + lane];
        float trans = __expf(lg - m) / ev;
        atomicAdd(&out[(size_t)eg * n_nodes + vjL], trans * att * ey);
    }
}

// ---------------------------------------------------------------------------
extern "C" void kernel_launch(void* const* d_in, const int* in_sizes, int n_in,
                              void* d_out, int out_size)
{
    const float* natt    = (const float*)d_in[0];
    const int*   edges   = (const int*)d_in[1];
    const float* edges_y = (const float*)d_in[2];
    const float* hu_in   = (const float*)d_in[3];   // [1, n_nodes, 256]
    const float* hc_in   = (const float*)d_in[4];   // [n_mem, 64]
    const float* Wc      = (const float*)d_in[5];
    const float* bc      = (const float*)d_in[6];
    const float* Wu      = (const float*)d_in[7];
    const float* bu      = (const float*)d_in[8];
    const float* rel_t   = (const float*)d_in[9];
    const float* ws      = (const float*)d_in[10];
    const float* fb      = (const float*)d_in[11];
    const float* ow      = (const float*)d_in[12];

    const int E       = in_sizes[2];
    const int n_nodes = in_sizes[3] / 256;
    const int n_mem   = in_sizes[4] / 64;
    const int n_seg   = E / 20;

    const int nb_c = (n_mem + 127) / 128;      // 1024
    const int nb_u = (n_nodes + 127) / 128;    // 391

    const int dyn_smem = 14336 * 4;            // 57,344 bytes
    cudaFuncSetAttribute(proj_both_kernel,
                         cudaFuncAttributeMaxDynamicSharedMemorySize, dyn_smem);
    cudaFuncSetAttribute(proj_both_kernel,
                         cudaFuncAttributePreferredSharedMemoryCarveout, 100);

    cudaMemsetAsync(d_out, 0, (size_t)out_size * sizeof(float));     // launch 1

    proj_both_kernel<<<nb_c + nb_u, 256, dyn_smem>>>(                // launch 2
        hc_in, Wc, bc, n_mem, hu_in, Wu, bu, n_nodes, nb_u);

    capture_align_kernel<<<1, 32>>>();                               // launch 3

    edge_kernel<<<n_seg / 2, 320>>>(natt, edges, edges_y, rel_t,     // launch 4
                                    ws, fb, ow, (float*)d_out, n_nodes);
}